// round 2
// baseline (speedup 1.0000x reference)
#include <cuda_runtime.h>
#include <stdint.h>

// SpectralConv1d: out[b,o,t] = Re( ICFT( W[i,o,k] * CFT(x)[b,i,k<64] ) )
// Fixed shapes: B=32, Ci=Co=64, n=4096, modes=64.
//
// Pipeline (all fp32, FFMA2-packed inner loops, 8-row register blocking):
//  k0: build trig tables  cos/-sin(2*pi*(k*j mod n)/n) in two layouts
//  k1: prep W  -> transposed [k][i][o], scaled by 1/n
//  k2: stage1  X[row=b*Ci+i][128] = x[2048x4096] @ T[4096x128]  (split-K 16)
//  k3: reduce split-K partials -> Xr[k][row], Xi[k][row] (k-major)
//  k4: stage2  Y[k][row=b*Co+o] = per-mode complex GEMM with W
//  k5: stage3  out[row][m] = (-1)^m * sum_k ( Yr*cos + Yi*(-sin) )

#define NT     4096
#define MODES  64
#define NB     32
#define NCI    64
#define NCO    64
#define ROWS   2048          // NB*NCI == NB*NCO
#define KSPLIT 16
#define KCHUNK 256           // NT / KSPLIT

// ---------------- device scratch (no allocations allowed) ----------------
__device__ float g_tabT[NT][2 * MODES];     // [t][c]: c<64 -> cos, c>=64 -> -sin   (2 MB)
__device__ float g_tabKc[MODES][NT];        // cos[k][j]                            (1 MB)
__device__ float g_tabKs[MODES][NT];        // -sin[k][j]                           (1 MB)
__device__ float g_part[KSPLIT][ROWS][2 * MODES];  // stage1 split-K partials       (16 MB)
__device__ float g_Xr[MODES][ROWS];         // k-major CFT result                   (512 KB)
__device__ float g_Xi[MODES][ROWS];
__device__ float g_Wr[MODES][NCI][NCO];     // transposed weights, * (1/NT)         (1 MB)
__device__ float g_Wi[MODES][NCI][NCO];
__device__ float g_Yr[MODES][ROWS];         // k-major spectral-mixed result
__device__ float g_Yi[MODES][ROWS];

// ---------------- packed fp32x2 helpers (FFMA2: ptx-only on sm_103a) -----
typedef unsigned long long ull_t;

__device__ __forceinline__ ull_t pack2(float lo, float hi) {
    ull_t r;
    asm("mov.b64 %0, {%1, %2};" : "=l"(r) : "f"(lo), "f"(hi));
    return r;
}
__device__ __forceinline__ ull_t fma2(ull_t a, ull_t b, ull_t c) {
    ull_t d;
    asm("fma.rn.f32x2 %0, %1, %2, %3;" : "=l"(d) : "l"(a), "l"(b), "l"(c));
    return d;
}
__device__ __forceinline__ float2 unpack2(ull_t v) {
    float2 f;
    asm("mov.b64 {%0, %1}, %2;" : "=f"(f.x), "=f"(f.y) : "l"(v));
    return f;
}

// ---------------- k0: trig tables ----------------------------------------
__global__ __launch_bounds__(256) void k_build_tables() {
    int idx = blockIdx.x * blockDim.x + threadIdx.x;   // 0 .. 64*4096-1
    int k = idx >> 12;
    int j = idx & (NT - 1);
    int r = (k * j) & (NT - 1);                        // exact periodic reduction
    const float w = (float)(6.283185307179586476925287 / (double)NT);
    float s, c;
    sincosf(w * (float)r, &s, &c);
    g_tabT[j][k]         = c;
    g_tabT[j][MODES + k] = -s;
    g_tabKc[k][j] = c;
    g_tabKs[k][j] = -s;
}

// ---------------- k1: transpose + scale W --------------------------------
__global__ __launch_bounds__(256) void k_prep_w(const float* __restrict__ wr,
                                                const float* __restrict__ wi) {
    int idx = blockIdx.x * blockDim.x + threadIdx.x;   // 0 .. 64*64*64-1
    int k = idx & 63;
    int o = (idx >> 6) & 63;
    int i = idx >> 12;
    const float sc = 1.0f / (float)NT;                 // bakes CFT's dt = 1/n
    int src = (i * NCO + o) * MODES + k;
    g_Wr[k][i][o] = wr[src] * sc;
    g_Wi[k][i][o] = wi[src] * sc;
}

// ---------------- k2: stage1 GEMM, split-K -------------------------------
// C[64 rows x 128 cols] += x[64 x 256] @ T[256 x 128], grid = (32 row-tiles, 16 k-splits)
// 128 threads, each computes 8 rows x 8 scalar cols (4 fma2 accumulators x 8 rows).
__global__ __launch_bounds__(128) void k_stage1(const float* __restrict__ x) {
    __shared__ float As[64][36];     // [row][kk], pad 36 (144B rows, 16B aligned)
    __shared__ float Bs[32][132];    // [kk][col], pad 132 (528B rows, 16B aligned)

    const int tx = threadIdx.x;
    const int rowBase = blockIdx.x * 64;
    const int kBase = blockIdx.y * KCHUNK;
    const int r0 = (tx >> 4) * 8;          // 8 rows per thread (8 groups x 8 = 64)
    const int c0 = (tx & 15) * 4;          // scalar cols {c0..c0+3} and {c0+64..c0+67}

    ull_t acc[8][4];
    #pragma unroll
    for (int i = 0; i < 8; i++)
        #pragma unroll
        for (int j = 0; j < 4; j++) acc[i][j] = pack2(0.f, 0.f);

    for (int t = 0; t < KCHUNK; t += 32) {
        // A tile: 64 rows x 32 k = 512 float4, 4 per thread
        #pragma unroll
        for (int q = 0; q < 4; q++) {
            int f = tx + q * 128;
            int r = f >> 3, j4 = (f & 7) * 4;
            float4 v = *(const float4*)&x[(size_t)(rowBase + r) * NT + kBase + t + j4];
            *(float4*)&As[r][j4] = v;
        }
        // B tile: 32 k x 128 cols = 1024 float4, 8 per thread
        #pragma unroll
        for (int q = 0; q < 8; q++) {
            int f = tx + q * 128;
            int jj = f >> 5, c4 = (f & 31) * 4;
            float4 v = *(const float4*)&g_tabT[kBase + t + jj][c4];
            *(float4*)&Bs[jj][c4] = v;
        }
        __syncthreads();

        #pragma unroll
        for (int kk = 0; kk < 32; kk++) {
            ulonglong2 bA = *(const ulonglong2*)&Bs[kk][c0];
            ulonglong2 bB = *(const ulonglong2*)&Bs[kk][c0 + 64];
            #pragma unroll
            for (int i = 0; i < 8; i++) {
                float a = As[r0 + i][kk];
                ull_t a2 = pack2(a, a);
                acc[i][0] = fma2(a2, bA.x, acc[i][0]);
                acc[i][1] = fma2(a2, bA.y, acc[i][1]);
                acc[i][2] = fma2(a2, bB.x, acc[i][2]);
                acc[i][3] = fma2(a2, bB.y, acc[i][3]);
            }
        }
        __syncthreads();
    }

    const int bk = blockIdx.y;
    #pragma unroll
    for (int i = 0; i < 8; i++) {
        float2 v0 = unpack2(acc[i][0]), v1 = unpack2(acc[i][1]);
        float2 v2 = unpack2(acc[i][2]), v3 = unpack2(acc[i][3]);
        float4 wA = make_float4(v0.x, v0.y, v1.x, v1.y);
        float4 wB = make_float4(v2.x, v2.y, v3.x, v3.y);
        *(float4*)&g_part[bk][rowBase + r0 + i][c0]      = wA;
        *(float4*)&g_part[bk][rowBase + r0 + i][c0 + 64] = wB;
    }
}

// ---------------- k3: reduce split-K, transpose to k-major ---------------
__global__ __launch_bounds__(256) void k_reduce1() {
    int idx = blockIdx.x * blockDim.x + threadIdx.x;   // 0 .. 2048*128-1
    int row = idx >> 7;
    int c = idx & 127;
    float s = 0.f;
    #pragma unroll
    for (int p = 0; p < KSPLIT; p++) s += g_part[p][row][c];
    if (c < MODES) g_Xr[c][row] = s;
    else           g_Xi[c - MODES][row] = s;
}

// ---------------- k4: stage2 per-mode complex mix ------------------------
// grid = (64 modes, 2 batch-halves), 256 threads
__global__ __launch_bounds__(256) void k_stage2() {
    __shared__ float sXr[1024], sXi[1024];
    __shared__ float sWr[64][64], sWi[64][64];

    const int k = blockIdx.x;
    const int b0 = blockIdx.y * 16;
    const int tx = threadIdx.x;
    const int rbase = b0 * NCI;

    #pragma unroll
    for (int q = 0; q < 4; q++) {
        int f = tx + q * 256;
        sXr[f] = g_Xr[k][rbase + f];
        sXi[f] = g_Xi[k][rbase + f];
    }
    const float* wrp = &g_Wr[k][0][0];
    const float* wip = &g_Wi[k][0][0];
    #pragma unroll
    for (int q = 0; q < 16; q++) {
        int f = tx + q * 256;
        ((float*)sWr)[f] = wrp[f];
        ((float*)sWi)[f] = wip[f];
    }
    __syncthreads();

    const int o = tx & 63;
    const int bl = tx >> 6;
    #pragma unroll
    for (int q = 0; q < 4; q++) {
        int b = bl * 4 + q;                 // local batch 0..15
        float ar = 0.f, ai = 0.f;
        #pragma unroll 8
        for (int i = 0; i < 64; i++) {
            float xr = sXr[b * 64 + i], xi = sXi[b * 64 + i];
            float wr = sWr[i][o], wi = sWi[i][o];
            ar = fmaf(xr, wr, ar);
            ar = fmaf(-xi, wi, ar);
            ai = fmaf(xr, wi, ai);
            ai = fmaf(xi, wr, ai);
        }
        g_Yr[k][rbase + b * 64 + o] = ar;   // row = (b0+b)*NCO + o
        g_Yi[k][rbase + b * 64 + o] = ai;
    }
}

// ---------------- k5: stage3 ICFT GEMM -----------------------------------
// out[64 rows x 128 times] per block; grid = (32 row-tiles, 32 time-tiles)
// 128 threads, each computes 8 rows x 8 scalar time-cols.
// dynamic smem: sYr[64*64] sYi[64*64] sC[64*128] sS[64*128] = 96 KB
__global__ __launch_bounds__(128) void k_stage3(float* __restrict__ out) {
    extern __shared__ float sm[];
    float* sYr = sm;              // [k][r] : sYr[k*64 + r]
    float* sYi = sm + 4096;
    float* sC  = sm + 8192;       // [k][c] : sC[k*128 + c]
    float* sS  = sm + 16384;

    const int tx = threadIdx.x;
    const int rowBase = blockIdx.x * 64;
    const int jBase = blockIdx.y * 128;

    #pragma unroll
    for (int q = 0; q < 8; q++) {            // Y: 64k x 64r floats each
        int f = tx + q * 128;
        int k = f >> 4, r4 = (f & 15) * 4;
        *(float4*)&sYr[k * 64 + r4] = *(const float4*)&g_Yr[k][rowBase + r4];
        *(float4*)&sYi[k * 64 + r4] = *(const float4*)&g_Yi[k][rowBase + r4];
    }
    #pragma unroll
    for (int q = 0; q < 16; q++) {           // tables: 64k x 128c floats each
        int f = tx + q * 128;
        int k = f >> 5, c4 = (f & 31) * 4;
        *(float4*)&sC[k * 128 + c4] = *(const float4*)&g_tabKc[k][jBase + c4];
        *(float4*)&sS[k * 128 + c4] = *(const float4*)&g_tabKs[k][jBase + c4];
    }
    __syncthreads();

    const int r0 = (tx >> 4) * 8;
    const int c0 = (tx & 15) * 4;

    ull_t acc[8][4];
    #pragma unroll
    for (int i = 0; i < 8; i++)
        #pragma unroll
        for (int j = 0; j < 4; j++) acc[i][j] = pack2(0.f, 0.f);

    #pragma unroll 2
    for (int k = 0; k < MODES; k++) {
        ulonglong2 cA = *(const ulonglong2*)&sC[k * 128 + c0];
        ulonglong2 cB = *(const ulonglong2*)&sC[k * 128 + c0 + 64];
        ulonglong2 sA = *(const ulonglong2*)&sS[k * 128 + c0];
        ulonglong2 sB = *(const ulonglong2*)&sS[k * 128 + c0 + 64];
        float4 yrA = *(const float4*)&sYr[k * 64 + r0];
        float4 yrB = *(const float4*)&sYr[k * 64 + r0 + 4];
        float4 yiA = *(const float4*)&sYi[k * 64 + r0];
        float4 yiB = *(const float4*)&sYi[k * 64 + r0 + 4];
        const float* yrf = &yrA.x;   // yrA,yrB contiguous in regs not guaranteed;
        const float* yif = &yiA.x;   // index each float4 explicitly below
        #pragma unroll
        for (int i = 0; i < 4; i++) {
            ull_t ar2 = pack2(yrf[i], yrf[i]);
            ull_t ai2 = pack2(yif[i], yif[i]);
            acc[i][0] = fma2(ar2, cA.x, acc[i][0]);
            acc[i][1] = fma2(ar2, cA.y, acc[i][1]);
            acc[i][2] = fma2(ar2, cB.x, acc[i][2]);
            acc[i][3] = fma2(ar2, cB.y, acc[i][3]);
            acc[i][0] = fma2(ai2, sA.x, acc[i][0]);
            acc[i][1] = fma2(ai2, sA.y, acc[i][1]);
            acc[i][2] = fma2(ai2, sB.x, acc[i][2]);
            acc[i][3] = fma2(ai2, sB.y, acc[i][3]);
        }
        const float* yrg = &yrB.x;
        const float* yig = &yiB.x;
        #pragma unroll
        for (int i = 0; i < 4; i++) {
            ull_t ar2 = pack2(yrg[i], yrg[i]);
            ull_t ai2 = pack2(yig[i], yig[i]);
            acc[4 + i][0] = fma2(ar2, cA.x, acc[4 + i][0]);
            acc[4 + i][1] = fma2(ar2, cA.y, acc[4 + i][1]);
            acc[4 + i][2] = fma2(ar2, cB.x, acc[4 + i][2]);
            acc[4 + i][3] = fma2(ar2, cB.y, acc[4 + i][3]);
            acc[4 + i][0] = fma2(ai2, sA.x, acc[4 + i][0]);
            acc[4 + i][1] = fma2(ai2, sA.y, acc[4 + i][1]);
            acc[4 + i][2] = fma2(ai2, sB.x, acc[4 + i][2]);
            acc[4 + i][3] = fma2(ai2, sB.y, acc[4 + i][3]);
        }
    }

    // epilogue: (-1)^m sign; jBase and c0 are even so signs alternate +,-
    #pragma unroll
    for (int i = 0; i < 8; i++) {
        float2 v0 = unpack2(acc[i][0]), v1 = unpack2(acc[i][1]);
        float2 v2 = unpack2(acc[i][2]), v3 = unpack2(acc[i][3]);
        float4 oA = make_float4(v0.x, -v0.y, v1.x, -v1.y);
        float4 oB = make_float4(v2.x, -v2.y, v3.x, -v3.y);
        size_t base = (size_t)(rowBase + r0 + i) * NT + jBase;
        *(float4*)&out[base + c0]      = oA;
        *(float4*)&out[base + c0 + 64] = oB;
    }
}

// ---------------- launch --------------------------------------------------
extern "C" void kernel_launch(void* const* d_in, const int* in_sizes, int n_in,
                              void* d_out, int out_size) {
    const float* x  = (const float*)d_in[0];
    const float* wr = (const float*)d_in[1];
    const float* wi = (const float*)d_in[2];
    float* out = (float*)d_out;

    k_build_tables<<<(MODES * NT) / 256, 256>>>();
    k_prep_w<<<(MODES * NCI * NCO) / 256, 256>>>(wr, wi);
    k_stage1<<<dim3(ROWS / 64, KSPLIT), 128>>>(x);
    k_reduce1<<<(ROWS * 2 * MODES) / 256, 256>>>();
    k_stage2<<<dim3(MODES, 2), 256>>>();

    const int smem3 = 24576 * (int)sizeof(float);    // 96 KB
    cudaFuncSetAttribute(k_stage3, cudaFuncAttributeMaxDynamicSharedMemorySize, smem3);
    k_stage3<<<dim3(ROWS / 64, NT / 128), 128, smem3>>>(out);
}

// round 10
// speedup vs baseline: 1.3248x; 1.3248x over previous
#include <cuda_runtime.h>
#include <cuda_bf16.h>
#include <stdint.h>

// SpectralConv1d: out[b,o,t] = Re( ICFT( W[i,o,k] * CFT(x)[b,i,k<64] ) )
// B=32, Ci=Co=64, n=4096, modes=64.
//
// Tensor-core pipeline (bf16-split 4-term exact GEMMs, fp32 accumulate):
//  k_tab1 : T1[c=0..127][t] = {cos,-sin}( fl(fl(2pi*k)*t) )  bf16 hi/lo, [n][t] layout
//  k_tab3 : T3[m][c=0..127]  = {cos,+sin}( fl(fl(2pi*t_m)*(k-2048)) ) bf16 hi/lo
//  k_prep_w: W -> [k][i][o] * (1/n)
//  k_stage1: X[2048x128] = x[2048x4096] @ T1^T   (mma.sync, split-K 16)
//  k_reduce1: sum partials -> Xr/Xi [k][row]
//  k_stage2: per-mode complex mix -> Yr/Yi [k][row] (fp32)
//  k_packY : transpose+split -> Ypack[row][128] bf16 hi/lo  ([Yr | -Yi])
//  k_stage3: out[2048x4096] = Ypack @ T3^T       (mma.sync, K=128)

#define NT     4096
#define MODES  64
#define ROWS   2048
#define KSPLIT 16
#define KCHUNK 256           // NT / KSPLIT

// ---------------- device scratch ----------------
__device__ float g_part[KSPLIT][ROWS][128];          // 16 MB
__device__ float g_Xr[MODES][ROWS], g_Xi[MODES][ROWS];
__device__ float g_Wr[MODES][64][64], g_Wi[MODES][64][64];
__device__ float g_Yr[MODES][ROWS], g_Yi[MODES][ROWS];
__device__ __align__(16) __nv_bfloat16 g_T1hi[128 * NT], g_T1lo[128 * NT];   // [n][t]
__device__ __align__(16) __nv_bfloat16 g_T3hi[NT * 128], g_T3lo[NT * 128];   // [m][k]
__device__ __align__(16) __nv_bfloat16 g_Yphi[ROWS * 128], g_Yplo[ROWS * 128];

// ---------------- helpers ----------------
__device__ __forceinline__ unsigned pack_bf2(__nv_bfloat16 a, __nv_bfloat16 b) {
    __nv_bfloat162 t = __halves2bfloat162(a, b);
    return *(unsigned*)&t;
}
__device__ __forceinline__ void split_bf(float v, __nv_bfloat16& h, __nv_bfloat16& l) {
    h = __float2bfloat16(v);
    l = __float2bfloat16(v - __bfloat162float(h));
}
__device__ __forceinline__ void ldsm4(unsigned* r, unsigned addr) {
    asm volatile("ldmatrix.sync.aligned.m8n8.x4.shared.b16 {%0,%1,%2,%3}, [%4];\n"
                 : "=r"(r[0]), "=r"(r[1]), "=r"(r[2]), "=r"(r[3]) : "r"(addr));
}
__device__ __forceinline__ void mma16816(float* d, const unsigned* a, unsigned b0, unsigned b1) {
    asm volatile("mma.sync.aligned.m16n8k16.row.col.f32.bf16.bf16.f32 "
                 "{%0,%1,%2,%3}, {%4,%5,%6,%7}, {%8,%9}, {%0,%1,%2,%3};\n"
                 : "+f"(d[0]), "+f"(d[1]), "+f"(d[2]), "+f"(d[3])
                 : "r"(a[0]), "r"(a[1]), "r"(a[2]), "r"(a[3]), "r"(b0), "r"(b1));
}

#define TWO_PI_F ((float)(2.0 * 3.14159265358979323846))

// ---------------- tables ----------------
__global__ __launch_bounds__(256) void k_tab1() {
    int idx = blockIdx.x * 256 + threadIdx.x;      // 64 * 4096
    int k = idx >> 12, j = idx & (NT - 1);
    float a = __fmul_rn(TWO_PI_F, (float)k);
    float th = __fmul_rn(a, (float)j * 0.000244140625f);   // t = j/4096 exact
    float s, c;
    sincosf(th, &s, &c);
    __nv_bfloat16 h, l;
    split_bf(c, h, l);
    g_T1hi[(size_t)k * NT + j] = h;  g_T1lo[(size_t)k * NT + j] = l;
    split_bf(-s, h, l);
    g_T1hi[(size_t)(k + 64) * NT + j] = h;  g_T1lo[(size_t)(k + 64) * NT + j] = l;
}

__global__ __launch_bounds__(256) void k_tab3() {
    int idx = blockIdx.x * 256 + threadIdx.x;      // 64 * 4096, m-major
    int m = idx >> 6, k = idx & 63;
    float tm = (float)m * 0.000244140625f;
    float a = __fmul_rn(TWO_PI_F, tm);
    float th = __fmul_rn(a, (float)(k - 2048));    // matches reference fp32 angle
    // exact double-precision periodic reduction of the fp32 angle
    double d = (double)th;
    double r = fma(-6.283185307179586476925287, rint(d * 0.15915494309189535), d);
    float s, c;
    sincosf((float)r, &s, &c);
    __nv_bfloat16 h, l;
    split_bf(c, h, l);
    g_T3hi[(size_t)m * 128 + k] = h;  g_T3lo[(size_t)m * 128 + k] = l;
    split_bf(s, h, l);
    g_T3hi[(size_t)m * 128 + 64 + k] = h;  g_T3lo[(size_t)m * 128 + 64 + k] = l;
}

// ---------------- prep W ----------------
__global__ __launch_bounds__(256) void k_prep_w(const float* __restrict__ wr,
                                                const float* __restrict__ wi) {
    int idx = blockIdx.x * 256 + threadIdx.x;      // 64*64*64
    int k = idx & 63, o = (idx >> 6) & 63, i = idx >> 12;
    const float sc = 1.0f / (float)NT;
    int src = (i * 64 + o) * MODES + k;
    g_Wr[k][i][o] = wr[src] * sc;
    g_Wi[k][i][o] = wi[src] * sc;
}

// ---------------- stage1: X = x @ T1^T  (split-K tensor GEMM) ----------------
// CTA 128 rows x 128 cols, 8 warps (4x2), KT=64 per smem tile, KCHUNK=256.
// smem regions (16KB each): Ahi@0 Alo@16384 Bhi@32768 Blo@49152. 64 KB dynamic.
__global__ __launch_bounds__(256) void k_stage1(const float* __restrict__ x) {
    extern __shared__ unsigned char sm1[];
    unsigned sbase = (unsigned)__cvta_generic_to_shared(sm1);
    const int tx = threadIdx.x, lane = tx & 31, wid = tx >> 5;
    const int wm = wid & 3, wn = wid >> 2;
    const int rowBase = blockIdx.x * 128;
    const int kBase = blockIdx.y * KCHUNK;

    float acc[2][8][4];
    #pragma unroll
    for (int i = 0; i < 2; i++)
        #pragma unroll
        for (int j = 0; j < 8; j++)
            #pragma unroll
            for (int q = 0; q < 4; q++) acc[i][j][q] = 0.f;

    for (int t = 0; t < KCHUNK; t += 64) {
        // A loader: 128 rows x 64 k fp32 -> bf16 hi/lo (fused split)
        #pragma unroll
        for (int q = 0; q < 8; q++) {
            int f = tx + q * 256;
            int r = f >> 4;
            int c4 = (f & 15) * 4;
            const float4 v = *(const float4*)(x + (size_t)(rowBase + r) * NT + kBase + t + c4);
            __nv_bfloat16 h0, h1, h2, h3, l0, l1, l2, l3;
            split_bf(v.x, h0, l0); split_bf(v.y, h1, l1);
            split_bf(v.z, h2, l2); split_bf(v.w, h3, l3);
            int byte = c4 * 2;
            int ch = byte >> 4;
            unsigned off = r * 128 + ((ch ^ (r & 7)) << 4) + (byte & 15);
            *(uint2*)(sm1 + off)         = make_uint2(pack_bf2(h0, h1), pack_bf2(h2, h3));
            *(uint2*)(sm1 + 16384 + off) = make_uint2(pack_bf2(l0, l1), pack_bf2(l2, l3));
        }
        // B loader: 128 n-rows x 64 k bf16 (hi & lo)
        #pragma unroll
        for (int q = 0; q < 4; q++) {
            int f = tx + q * 256;
            int n = f >> 3, ch = f & 7;
            size_t src = (size_t)n * NT + kBase + t + ch * 8;   // halfword idx
            unsigned off = n * 128 + ((ch ^ (n & 7)) << 4);
            *(uint4*)(sm1 + 32768 + off) = *(const uint4*)(g_T1hi + src);
            *(uint4*)(sm1 + 49152 + off) = *(const uint4*)(g_T1lo + src);
        }
        __syncthreads();

        #pragma unroll
        for (int ks = 0; ks < 4; ks++) {
            unsigned ah[2][4], al[2][4], bb[4][4];
            #pragma unroll
            for (int mi = 0; mi < 2; mi++) {
                int r = wm * 32 + mi * 16 + (lane & 15);
                int ch = ks * 2 + (lane >> 4);
                unsigned off = r * 128 + ((ch ^ (r & 7)) << 4);
                ldsm4(ah[mi], sbase + off);
                ldsm4(al[mi], sbase + 16384 + off);
            }
            #pragma unroll
            for (int ng = 0; ng < 4; ng++) {
                int n = wn * 64 + ng * 16 + (lane & 15);
                int ch = ks * 2 + (lane >> 4);
                unsigned off = n * 128 + ((ch ^ (n & 7)) << 4);
                ldsm4(bb[ng], sbase + 32768 + off);
            }
            #pragma unroll
            for (int mi = 0; mi < 2; mi++)
                #pragma unroll
                for (int ng = 0; ng < 4; ng++) {
                    mma16816(acc[mi][ng * 2],     ah[mi], bb[ng][0], bb[ng][2]);
                    mma16816(acc[mi][ng * 2 + 1], ah[mi], bb[ng][1], bb[ng][3]);
                    mma16816(acc[mi][ng * 2],     al[mi], bb[ng][0], bb[ng][2]);
                    mma16816(acc[mi][ng * 2 + 1], al[mi], bb[ng][1], bb[ng][3]);
                }
            #pragma unroll
            for (int ng = 0; ng < 4; ng++) {
                int n = wn * 64 + ng * 16 + (lane & 15);
                int ch = ks * 2 + (lane >> 4);
                unsigned off = n * 128 + ((ch ^ (n & 7)) << 4);
                ldsm4(bb[ng], sbase + 49152 + off);
            }
            #pragma unroll
            for (int mi = 0; mi < 2; mi++)
                #pragma unroll
                for (int ng = 0; ng < 4; ng++) {
                    mma16816(acc[mi][ng * 2],     ah[mi], bb[ng][0], bb[ng][2]);
                    mma16816(acc[mi][ng * 2 + 1], ah[mi], bb[ng][1], bb[ng][3]);
                    mma16816(acc[mi][ng * 2],     al[mi], bb[ng][0], bb[ng][2]);
                    mma16816(acc[mi][ng * 2 + 1], al[mi], bb[ng][1], bb[ng][3]);
                }
        }
        __syncthreads();
    }

    float* pout = &g_part[blockIdx.y][0][0];
    #pragma unroll
    for (int mi = 0; mi < 2; mi++)
        #pragma unroll
        for (int n8 = 0; n8 < 8; n8++) {
            int row0 = rowBase + wm * 32 + mi * 16 + (lane >> 2);
            int col = wn * 64 + n8 * 8 + (lane & 3) * 2;
            float* p = pout + (size_t)row0 * 128 + col;
            *(float2*)p             = make_float2(acc[mi][n8][0], acc[mi][n8][1]);
            *(float2*)(p + 8 * 128) = make_float2(acc[mi][n8][2], acc[mi][n8][3]);
        }
}

// ---------------- reduce split-K -> k-major Xr/Xi ----------------
__global__ __launch_bounds__(256) void k_reduce1() {
    __shared__ float s[128][9];
    const int tx = threadIdx.x;
    const int rowBase = blockIdx.x * 8;
    const int r = tx >> 5, c4 = tx & 31;
    float4 a = make_float4(0.f, 0.f, 0.f, 0.f);
    #pragma unroll
    for (int p = 0; p < KSPLIT; p++) {
        const float4 v = *(const float4*)&g_part[p][rowBase + r][c4 * 4];
        a.x += v.x; a.y += v.y; a.z += v.z; a.w += v.w;
    }
    s[c4 * 4 + 0][r] = a.x; s[c4 * 4 + 1][r] = a.y;
    s[c4 * 4 + 2][r] = a.z; s[c4 * 4 + 3][r] = a.w;
    __syncthreads();
    const int c = tx >> 1, h = tx & 1;
    float4 v = make_float4(s[c][h * 4], s[c][h * 4 + 1], s[c][h * 4 + 2], s[c][h * 4 + 3]);
    if (c < 64) *(float4*)&g_Xr[c][rowBase + h * 4] = v;
    else        *(float4*)&g_Xi[c - 64][rowBase + h * 4] = v;
}

// ---------------- stage2: per-mode complex mix (fp32) ----------------
__global__ __launch_bounds__(256) void k_stage2() {
    __shared__ float sXr[1024], sXi[1024];
    __shared__ float sWr[64][64], sWi[64][64];
    const int k = blockIdx.x;
    const int b0 = blockIdx.y * 16;
    const int tx = threadIdx.x;
    const int rbase = b0 * 64;
    #pragma unroll
    for (int q = 0; q < 4; q++) {
        int f = tx + q * 256;
        sXr[f] = g_Xr[k][rbase + f];
        sXi[f] = g_Xi[k][rbase + f];
    }
    const float* wrp = &g_Wr[k][0][0];
    const float* wip = &g_Wi[k][0][0];
    #pragma unroll
    for (int q = 0; q < 16; q++) {
        int f = tx + q * 256;
        ((float*)sWr)[f] = wrp[f];
        ((float*)sWi)[f] = wip[f];
    }
    __syncthreads();
    const int o = tx & 63, bl = tx >> 6;
    #pragma unroll
    for (int q = 0; q < 4; q++) {
        int b = bl * 4 + q;
        float ar = 0.f, ai = 0.f;
        #pragma unroll 8
        for (int i = 0; i < 64; i++) {
            float xr = sXr[b * 64 + i], xi = sXi[b * 64 + i];
            float wr = sWr[i][o], wi = sWi[i][o];
            ar = fmaf(xr, wr, ar);
            ar = fmaf(-xi, wi, ar);
            ai = fmaf(xr, wi, ai);
            ai = fmaf(xi, wr, ai);
        }
        g_Yr[k][rbase + b * 64 + o] = ar;
        g_Yi[k][rbase + b * 64 + o] = ai;
    }
}

// ---------------- packY: [k][row] fp32 -> [row][128] bf16 hi/lo ----------------
// Columns [Yr | -Yi] pair with T3 columns [cos | +sin]:
// out = Yr*cos + (-Yi)*sin = Re(Y * e^{+i th}). Minus applied exactly once (fp32).
__global__ __launch_bounds__(256) void k_packY() {
    __shared__ float s[32][129];
    const int tx = threadIdx.x;
    const int rowBase = blockIdx.x * 32;
    const int r = tx & 31, k2 = tx >> 5;
    #pragma unroll
    for (int kk = 0; kk < 8; kk++) {
        int k = kk * 8 + k2;
        s[r][k]      = g_Yr[k][rowBase + r];
        s[r][64 + k] = -g_Yi[k][rowBase + r];   // minus folded here (exact)
    }
    __syncthreads();
    #pragma unroll
    for (int q = 0; q < 16; q++) {
        int f = tx + q * 256;
        int rr = f >> 7, c = f & 127;
        float v = s[rr][c];
        __nv_bfloat16 h, l;
        split_bf(v, h, l);
        g_Yphi[(size_t)(rowBase + rr) * 128 + c] = h;
        g_Yplo[(size_t)(rowBase + rr) * 128 + c] = l;
    }
}

// ---------------- stage3: out = Ypack @ T3^T  (K=128 tensor GEMM) ----------------
// CTA 128 rows x 128 time-cols; smem 8 regions of 16KB:
// [Ahi0 Ahi1 Alo0 Alo1 Bhi0 Bhi1 Blo0 Blo1] = 128 KB dynamic.
__global__ __launch_bounds__(256) void k_stage3(float* __restrict__ out) {
    extern __shared__ unsigned char sm3[];
    unsigned sbase = (unsigned)__cvta_generic_to_shared(sm3);
    const int tx = threadIdx.x, lane = tx & 31, wid = tx >> 5;
    const int wm = wid & 3, wn = wid >> 2;
    const int rowBase = blockIdx.x * 128;
    const int jBase = blockIdx.y * 128;

    #pragma unroll
    for (int q = 0; q < 8; q++) {          // A: Ypack hi/lo
        int f = tx + q * 256;
        int r = f >> 4, chf = f & 15;
        int reg = chf >> 3, ch = chf & 7;
        unsigned off = (unsigned)reg * 16384 + r * 128 + ((ch ^ (r & 7)) << 4);
        size_t src = (size_t)(rowBase + r) * 128 + chf * 8;
        *(uint4*)(sm3 + off)         = *(const uint4*)(g_Yphi + src);
        *(uint4*)(sm3 + 32768 + off) = *(const uint4*)(g_Yplo + src);
    }
    #pragma unroll
    for (int q = 0; q < 8; q++) {          // B: T3 hi/lo
        int f = tx + q * 256;
        int n = f >> 4, chf = f & 15;
        int reg = chf >> 3, ch = chf & 7;
        unsigned off = 65536u + (unsigned)reg * 16384 + n * 128 + ((ch ^ (n & 7)) << 4);
        size_t src = (size_t)(jBase + n) * 128 + chf * 8;
        *(uint4*)(sm3 + off)         = *(const uint4*)(g_T3hi + src);
        *(uint4*)(sm3 + 32768 + off) = *(const uint4*)(g_T3lo + src);
    }
    __syncthreads();

    float acc[2][8][4];
    #pragma unroll
    for (int i = 0; i < 2; i++)
        #pragma unroll
        for (int j = 0; j < 8; j++)
            #pragma unroll
            for (int q = 0; q < 4; q++) acc[i][j][q] = 0.f;

    #pragma unroll
    for (int kt = 0; kt < 2; kt++) {
        unsigned aHi = sbase + kt * 16384;
        unsigned aLo = sbase + 32768 + kt * 16384;
        unsigned bHi = sbase + 65536 + kt * 16384;
        unsigned bLo = sbase + 98304 + kt * 16384;
        #pragma unroll
        for (int ks = 0; ks < 4; ks++) {
            unsigned ah[2][4], al[2][4], bb[4][4];
            #pragma unroll
            for (int mi = 0; mi < 2; mi++) {
                int r = wm * 32 + mi * 16 + (lane & 15);
                int ch = ks * 2 + (lane >> 4);
                unsigned off = r * 128 + ((ch ^ (r & 7)) << 4);
                ldsm4(ah[mi], aHi + off);
                ldsm4(al[mi], aLo + off);
            }
            #pragma unroll
            for (int ng = 0; ng < 4; ng++) {
                int n = wn * 64 + ng * 16 + (lane & 15);
                int ch = ks * 2 + (lane >> 4);
                unsigned off = n * 128 + ((ch ^ (n & 7)) << 4);
                ldsm4(bb[ng], bHi + off);
            }
            #pragma unroll
            for (int mi = 0; mi < 2; mi++)
                #pragma unroll
                for (int ng = 0; ng < 4; ng++) {
                    mma16816(acc[mi][ng * 2],     ah[mi], bb[ng][0], bb[ng][2]);
                    mma16816(acc[mi][ng * 2 + 1], ah[mi], bb[ng][1], bb[ng][3]);
                    mma16816(acc[mi][ng * 2],     al[mi], bb[ng][0], bb[ng][2]);
                    mma16816(acc[mi][ng * 2 + 1], al[mi], bb[ng][1], bb[ng][3]);
                }
            #pragma unroll
            for (int ng = 0; ng < 4; ng++) {
                int n = wn * 64 + ng * 16 + (lane & 15);
                int ch = ks * 2 + (lane >> 4);
                unsigned off = n * 128 + ((ch ^ (n & 7)) << 4);
                ldsm4(bb[ng], bLo + off);
            }
            #pragma unroll
            for (int mi = 0; mi < 2; mi++)
                #pragma unroll
                for (int ng = 0; ng < 4; ng++) {
                    mma16816(acc[mi][ng * 2],     ah[mi], bb[ng][0], bb[ng][2]);
                    mma16816(acc[mi][ng * 2 + 1], ah[mi], bb[ng][1], bb[ng][3]);
                    mma16816(acc[mi][ng * 2],     al[mi], bb[ng][0], bb[ng][2]);
                    mma16816(acc[mi][ng * 2 + 1], al[mi], bb[ng][1], bb[ng][3]);
                }
        }
    }

    #pragma unroll
    for (int mi = 0; mi < 2; mi++)
        #pragma unroll
        for (int n8 = 0; n8 < 8; n8++) {
            int row0 = rowBase + wm * 32 + mi * 16 + (lane >> 2);
            int col = jBase + wn * 64 + n8 * 8 + (lane & 3) * 2;
            float* p = out + (size_t)row0 * NT + col;
            *(float2*)p            = make_float2(acc[mi][n8][0], acc[mi][n8][1]);
            *(float2*)(p + 8 * NT) = make_float2(acc[mi][n8][2], acc[mi][n8][3]);
        }
}

// ---------------- launch ----------------
extern "C" void kernel_launch(void* const* d_in, const int* in_sizes, int n_in,
                              void* d_out, int out_size) {
    const float* x  = (const float*)d_in[0];
    const float* wr = (const float*)d_in[1];
    const float* wi = (const float*)d_in[2];
    float* out = (float*)d_out;

    cudaFuncSetAttribute(k_stage1, cudaFuncAttributeMaxDynamicSharedMemorySize, 65536);
    cudaFuncSetAttribute(k_stage3, cudaFuncAttributeMaxDynamicSharedMemorySize, 131072);

    k_tab1<<<(MODES * NT) / 256, 256>>>();
    k_tab3<<<(MODES * NT) / 256, 256>>>();
    k_prep_w<<<(MODES * 64 * 64) / 256, 256>>>(wr, wi);
    k_stage1<<<dim3(ROWS / 128, KSPLIT), 256, 65536>>>(x);
    k_reduce1<<<ROWS / 8, 256>>>();
    k_stage2<<<dim3(MODES, 2), 256>>>();
    k_packY<<<ROWS / 32, 256>>>();
    k_stage3<<<dim3(ROWS / 128, NT / 128), 256, 131072>>>(out);
}